// round 3
// baseline (speedup 1.0000x reference)
#include <cuda_runtime.h>

// CRF negative log-likelihood, T=512 B=64 L=48, START=46, STOP=47.
//
// forward: p_t[j] = f_t[j] + lse_i(p_{t-1}[i] + Tr[i][j]), t = 1..len-1
//          init p_0 = f_0 + Tr[START]; fwd_b = lse_i(p_len[i] + Tr[i][STOP])
// Linear-space with carried log offset, normalized by u[0]:
//   s_j   = sum_i u_{t-1}[i] * E[i][j],       E = exp(Tr)
//   u_t[j]= s_j * exp(f_t[j]-f_t[0]) / u_{t-1}[0]
//   C_t   = C_{t-1} + f_t[0] + ln u_{t-1}[0]
//
// Inputs are resolved by EVIDENCE, not assumed order:
//  - feats (1572864 elems) and transitions (2304 elems) found via in_sizes.
//  - the two 32768-elem buffers (tags / mask) are told apart on-device:
//    bool mask bytes are all {0,1}; tags have bytes >= 2 w.h.p.
//  - tags dtype (i32/i64) and mask width (1B/4B) also detected on-device.

#define TT 512
#define BB 64
#define LLAB 48
#define START_TAG 46
#define STOP_TAG 47
#define NT 96
#define L2E 1.4426950408889634f
#define LN2f 0.6931471805599453f
#define FSTRIDE (BB * LLAB)   // 3072 floats per time step

__device__ float g_partial[BB];
__device__ int   g_swap;    // 1 => candA is mask (tags = candB)
__device__ int   g_tag32;   // 1 => tags are int32
__device__ int   g_mask8;   // 1 => mask elements are 1 byte

__global__ void crf_setup(const unsigned int* candA, const unsigned int* candB) {
    const int tid = threadIdx.x;               // 64 threads
    __shared__ int s_bigA, s_oddnz;
    if (tid == 0) { s_bigA = 0; s_oddnz = 0; }
    __syncthreads();
    // candA word tid (bytes 4*tid..4*tid+3): any byte >= 2 ?
    unsigned wa = candA[tid];
    if ((wa & 0xFEFEFEFEu) != 0) atomicOr(&s_bigA, 1);
    __syncthreads();
    const int swap = (s_bigA == 0);            // no byte>1 => candA is the bool mask
    const unsigned int* tagp  = swap ? candB : candA;
    const unsigned int* maskp = swap ? candA : candB;
    // tags dtype: odd 32-bit words of an int64 buffer (values < 48) are all 0
    unsigned wo = tagp[2 * tid + 1];
    if (wo != 0) atomicOr(&s_oddnz, 1);
    __syncthreads();
    if (tid == 0) {
        g_swap  = swap;
        g_tag32 = s_oddnz;
        // 1-byte mask: byte 1 of word 0 is mask[0][1] = 1 (len >= 256 >> 2).
        // 4-byte mask: word 0 = 0x00000001, byte 1 = 0.
        g_mask8 = ((maskp[0] & 0x0000FF00u) != 0) ? 1 : 0;
    }
}

__device__ __forceinline__ int get_tag(const void* tags, int idx, int is32) {
    int v = is32 ? ((const int*)tags)[idx]
                 : (int)((const long long*)tags)[idx];
    return v < 0 ? 0 : (v > 47 ? 47 : v);      // clamp: OOB-proof
}
__device__ __forceinline__ int get_mask(const void* mask, int idx, int is8) {
    return is8 ? (int)((const unsigned char*)mask)[idx]
               : (((const int*)mask)[idx] != 0);
}

__global__ __launch_bounds__(NT, 1) void crf_fwd_kernel(
    const float* __restrict__ feats,      // (T, B, L)
    const float* __restrict__ trans,      // (L, L)
    const void*  __restrict__ candA,
    const void*  __restrict__ candB)
{
    const int b    = blockIdx.x;
    const int tid  = threadIdx.x;
    const int j    = tid >> 1;    // output state 0..47
    const int h    = tid & 1;     // which half of the i-range
    const int w    = tid >> 5;    // warp id 0..2
    const int lane = tid & 31;

    const int swap = g_swap, is32 = g_tag32, is8 = g_mask8;
    const void* tags = swap ? candB : candA;
    const void* mask = swap ? candA : candB;

    __shared__ __align__(16) float s_u[2][LLAB];  // ping-pong partition (linear)
    __shared__ float s_gwarp[3];
    __shared__ float s_gold;
    __shared__ int   s_len;

    if (tid == 0) s_len = 0;
    __syncthreads();

    // ---------------- gold path score (parallel over t) + length -----------
    {
        float gpart = 0.0f;
        int   lpart = 0;
        for (int t = tid; t < TT; t += NT) {
            if (get_mask(mask, b * TT + t, is8)) {
                lpart++;
                int tag  = get_tag(tags, b * TT + t, is32);
                int prev = (t == 0) ? START_TAG : get_tag(tags, b * TT + t - 1, is32);
                gpart += feats[t * FSTRIDE + b * LLAB + tag]
                       + trans[prev * LLAB + tag];
            }
        }
        // deterministic fixed-order reduction: warp shfl then 3-term sum
        #pragma unroll
        for (int off = 16; off > 0; off >>= 1)
            gpart += __shfl_xor_sync(0xffffffffu, gpart, off);
        if (lane == 0) s_gwarp[w] = gpart;
        atomicAdd(&s_len, lpart);   // integer: deterministic
    }

    // ---------------- per-thread E column slice (registers) ----------------
    float Ereg[24];
    #pragma unroll
    for (int r = 0; r < 24; ++r)
        Ereg[r] = expf(trans[(24 * h + r) * LLAB + j]);

    // ---------------- init: p_0 = f_0 + Tr[START][:] ------------------------
    const float* fb = feats + b * LLAB;
    float p00 = fb[0] + trans[START_TAG * LLAB + 0];
    float p0j = fb[j] + trans[START_TAG * LLAB + j];
    if (h == 0) s_u[0][j] = exp2f((p0j - p00) * L2E);
    float Cacc  = p00;    // log-offset, accumulated redundantly in all threads
    float Clog2 = 0.0f;

    __syncthreads();
    int len = s_len;                     // lengths in [256, 512]
    len = len < 2 ? 2 : (len > TT ? TT : len);

    if (tid == 0) {
        int endid = get_tag(tags, b * TT + len - 1, is32);
        s_gold = (s_gwarp[0] + s_gwarp[1] + s_gwarp[2])
               + trans[endid * LLAB + STOP_TAG];
    }

    // ---------------- forward recursion, distance-2 feats prefetch ----------
    float fjA = fb[1 * FSTRIDE + j];
    float f0A = fb[1 * FSTRIDE + 0];
    int   t2  = (2 < len) ? 2 : (len - 1);
    float fjB = fb[t2 * FSTRIDE + j];
    float f0B = fb[t2 * FSTRIDE + 0];

    for (int t = 1; t < len; ++t) {
        int tp = t + 2; if (tp > len - 1) tp = len - 1;
        float fjC = fb[tp * FSTRIDE + j];
        float f0C = fb[tp * FSTRIDE + 0];

        __syncthreads();                       // u[(t-1)&1] fully written
        const float* uin = s_u[(t - 1) & 1];
        float u0 = uin[0];
        Clog2 += log2f(u0);
        Cacc  += f0A;

        float a0 = 0.f, a1 = 0.f, a2 = 0.f, a3 = 0.f;
        const float4* u4 = reinterpret_cast<const float4*>(uin + 24 * h);
        #pragma unroll
        for (int r = 0; r < 6; ++r) {
            float4 v = u4[r];
            a0 = fmaf(v.x, Ereg[4 * r + 0], a0);
            a1 = fmaf(v.y, Ereg[4 * r + 1], a1);
            a2 = fmaf(v.z, Ereg[4 * r + 2], a2);
            a3 = fmaf(v.w, Ereg[4 * r + 3], a3);
        }
        float s = (a0 + a1) + (a2 + a3);
        s += __shfl_xor_sync(0xffffffffu, s, 1);   // combine the two halves

        float e    = exp2f((fjA - f0A) * L2E);
        float unew = __fdividef(s * e, u0);
        if (h == 0) s_u[t & 1][j] = unew;

        fjA = fjB; f0A = f0B; fjB = fjC; f0B = f0C;
    }

    __syncthreads();

    // ---------------- final transition to STOP ------------------------------
    if (j == STOP_TAG) {            // tid 94, 95 (lanes 30, 31 of warp 2)
        const float* uin = s_u[(len - 1) & 1];
        float a0 = 0.f, a1 = 0.f, a2 = 0.f, a3 = 0.f;
        const float4* u4 = reinterpret_cast<const float4*>(uin + 24 * h);
        #pragma unroll
        for (int r = 0; r < 6; ++r) {
            float4 v = u4[r];
            a0 = fmaf(v.x, Ereg[4 * r + 0], a0);
            a1 = fmaf(v.y, Ereg[4 * r + 1], a1);
            a2 = fmaf(v.z, Ereg[4 * r + 2], a2);
            a3 = fmaf(v.w, Ereg[4 * r + 3], a3);
        }
        float s = (a0 + a1) + (a2 + a3);
        s += __shfl_xor_sync(0xC0000000u, s, 1);
        if (h == 0) {
            float fwd = Cacc + (Clog2 + log2f(s)) * LN2f;
            g_partial[b] = fwd - s_gold;
        }
    }
}

__global__ void crf_reduce_kernel(float* __restrict__ out) {
    int tid = threadIdx.x;                       // 32 threads
    float v = g_partial[tid] + g_partial[tid + 32];
    #pragma unroll
    for (int off = 16; off > 0; off >>= 1)
        v += __shfl_xor_sync(0xffffffffu, v, off);
    if (tid == 0) out[0] = v;
}

extern "C" void kernel_launch(void* const* d_in, const int* in_sizes, int n_in,
                              void* d_out, int out_size) {
    // Resolve inputs by element count (order-independent).
    const float* feats = nullptr;
    const float* trans = nullptr;
    const void*  candA = nullptr;
    const void*  candB = nullptr;
    for (int i = 0; i < n_in; ++i) {
        long long c = in_sizes[i];
        if      (c == (long long)TT * BB * LLAB) feats = (const float*)d_in[i];
        else if (c == (long long)LLAB * LLAB)    trans = (const float*)d_in[i];
        else if (!candA)                         candA = d_in[i];
        else                                     candB = d_in[i];
    }

    crf_setup<<<1, 64>>>((const unsigned int*)candA, (const unsigned int*)candB);
    crf_fwd_kernel<<<BB, NT>>>(feats, trans, candA, candB);
    crf_reduce_kernel<<<1, 32>>>((float*)d_out);
}